// round 10
// baseline (speedup 1.0000x reference)
#include <cuda_runtime.h>
#include <cstdint>

// Fixed problem shape: N=320000, C=64, B=4, NY=496, NX=432, NZ=1
#define NY_   496
#define NX_   432
#define C_    64
#define B_    4
#define NCELL (B_ * NY_ * NX_)        // 857,088 cells

#define CCH    16                     // channels per chunk (4 chunks)
#define PITCH  436                    // SMEM pitch (432+4, multiple of 4)
#define THREADS_G 512

// Winner encoding: 0 = empty, w = point_index + 1.
// __device__ globals are zero-initialized at module load; the gather kernel
// re-zeroes each block's winner segment after consuming it, so the array is
// all-zero at every kernel_launch entry (identical state -> deterministic).
__device__ int4 g_winner4[NCELL / 4];

// ---------------------------------------------------------------------------
// Kernel 1: atomicMax scatter of (point index + 1). Last-write-wins == max.
// coors rows: (b, z, y, x), z == 0 always (NZ=1).
// ---------------------------------------------------------------------------
__global__ void scatter_winner_kernel(const int* __restrict__ coors, int n) {
    int i = blockIdx.x * blockDim.x + threadIdx.x;
    if (i < n) {
        int4 cz = *reinterpret_cast<const int4*>(coors + 4 * i);
        int cell = (cz.x * NY_ + cz.z) * NX_ + cz.w;
        atomicMax(reinterpret_cast<int*>(g_winner4) + cell, i + 1);
    }
}

// ---------------------------------------------------------------------------
// Kernel 2: one block per (b, y) row — 432 cells x 64 channels, 4 chunks of
// 16 channels through a transposed SMEM tile.  (R5-proven structure.)
//   Phase 0: 432 winners -> SMEM (108 int4), then reset them to 0 in GMEM.
//   Phase 2 (per chunk): thread = cell (t < 432); 4x LDG.128 (64 B feature
//       slice, MLP=4), transpose-store 16 scalars (stride-1 STS).
//   Phase 3 (per chunk): q-loop over 16 ch x 108 float4; plain STG.128.
// Static SMEM: 432*4 + 16*436*4 = 29,632 B.
// ---------------------------------------------------------------------------
__global__ __launch_bounds__(THREADS_G) void gather_row_kernel(
    const float* __restrict__ feat, float* __restrict__ out) {

    __shared__ int   sw[NX_];              // 1.7 KB
    __shared__ float tile[CCH * PITCH];    // 27.9 KB

    int t = threadIdx.x;
    int p = blockIdx.x;                    // 0 .. B*NY-1  (1984)
    int cell0 = p * NX_;                   // contiguous winner segment

    // Phase 0: copy winners to SMEM, then zero them for the next replay.
    if (t < NX_ / 4) {
        int4 w4 = g_winner4[cell0 / 4 + t];
        *reinterpret_cast<int4*>(sw + 4 * t) = w4;
        g_winner4[cell0 / 4 + t] = make_int4(0, 0, 0, 0);
    }
    __syncthreads();

    int b = p / NY_;
    int y = p - b * NY_;
    size_t rowbase = ((size_t)(b * C_) * NY_ + y) * NX_;

    #pragma unroll
    for (int cc = 0; cc < C_; cc += CCH) {
        // Phase 2: gather + transpose 16-channel slice, thread = cell
        if (t < NX_) {
            int w = sw[t];
            float4 v0 = make_float4(0.f, 0.f, 0.f, 0.f);
            float4 v1 = v0, v2 = v0, v3 = v0;
            if (w > 0) {
                const float4* src = reinterpret_cast<const float4*>(
                    feat + (size_t)(w - 1) * C_ + cc);
                v0 = src[0]; v1 = src[1]; v2 = src[2]; v3 = src[3];
            }
            tile[ 0 * PITCH + t] = v0.x;  tile[ 1 * PITCH + t] = v0.y;
            tile[ 2 * PITCH + t] = v0.z;  tile[ 3 * PITCH + t] = v0.w;
            tile[ 4 * PITCH + t] = v1.x;  tile[ 5 * PITCH + t] = v1.y;
            tile[ 6 * PITCH + t] = v1.z;  tile[ 7 * PITCH + t] = v1.w;
            tile[ 8 * PITCH + t] = v2.x;  tile[ 9 * PITCH + t] = v2.y;
            tile[10 * PITCH + t] = v2.z;  tile[11 * PITCH + t] = v2.w;
            tile[12 * PITCH + t] = v3.x;  tile[13 * PITCH + t] = v3.y;
            tile[14 * PITCH + t] = v3.z;  tile[15 * PITCH + t] = v3.w;
        }
        __syncthreads();

        // Phase 3: 16 channels * 108 float4 = 1728 vector stores, 3.375/thread
        for (int q = t; q < CCH * (NX_ / 4); q += THREADS_G) {
            int k = q / (NX_ / 4);
            int g = q - k * (NX_ / 4);
            float4 v = *reinterpret_cast<const float4*>(&tile[k * PITCH + g * 4]);
            *reinterpret_cast<float4*>(
                out + rowbase + (size_t)(cc + k) * (NY_ * NX_) + g * 4) = v;
        }
        __syncthreads();
    }
}

// ---------------------------------------------------------------------------
extern "C" void kernel_launch(void* const* d_in, const int* in_sizes, int n_in,
                              void* d_out, int out_size) {
    const float* feat  = (const float*)d_in[0];   // [N, 64] float32
    const int*   coors = (const int*)d_in[1];     // [N, 4] int32
    (void)n_in; (void)out_size;

    int n = in_sizes[1] / 4;

    {   // 1) atomicMax (point index + 1); winner array is all-zero on entry
        int threads = 256;
        int blocks  = (n + threads - 1) / threads;
        scatter_winner_kernel<<<blocks, threads>>>(coors, n);
    }
    {   // 2) row gather + transpose (+ winner reset for next replay)
        int blocks = B_ * NY_;   // 1984
        gather_row_kernel<<<blocks, THREADS_G>>>(feat, (float*)d_out);
    }
}

// round 11
// speedup vs baseline: 1.0272x; 1.0272x over previous
#include <cuda_runtime.h>
#include <cstdint>

// Fixed problem shape: N=320000, C=64, B=4, NY=496, NX=432, NZ=1
#define NY_   496
#define NX_   432
#define C_    64
#define B_    4
#define NCELL (B_ * NY_ * NX_)        // 857,088 cells

#define CCH    16                     // channels per chunk (4 chunks)
#define PITCH  436                    // SMEM pitch (432+4, multiple of 4)
#define THREADS_G 512

// Winner encoding: 0 = empty, w = point_index + 1.
// __device__ globals are zero-initialized at module load; the gather kernel
// re-zeroes each block's winner segment after consuming it, so the array is
// all-zero at every kernel_launch entry (identical state -> deterministic).
__device__ int4 g_winner4[NCELL / 4];

// ---------------------------------------------------------------------------
// Kernel 1: atomicMax scatter of (point index + 1). Last-write-wins == max.
// coors rows: (b, z, y, x), z == 0 always (NZ=1).
// ---------------------------------------------------------------------------
__global__ void scatter_winner_kernel(const int* __restrict__ coors, int n) {
    int i = blockIdx.x * blockDim.x + threadIdx.x;
    if (i < n) {
        int4 cz = *reinterpret_cast<const int4*>(coors + 4 * i);
        int cell = (cz.x * NY_ + cz.z) * NX_ + cz.w;
        atomicMax(reinterpret_cast<int*>(g_winner4) + cell, i + 1);
    }
}

// ---------------------------------------------------------------------------
// Kernel 2: one block per (b, y) row — 432 cells x 64 channels, 4 chunks of
// 16 channels through a transposed SMEM tile, SOFTWARE-PIPELINED:
//   the 4 feature LDG.128s for chunk cc+1 are issued right after the
//   STS->LDS sync of chunk cc, overlapping with phase-3's LDS/STG stream,
//   so no phase ever blocks on global-load latency.
// Static SMEM: 432*4 + 16*436*4 = 29,632 B  (4 blocks/SM).
// ---------------------------------------------------------------------------
__global__ __launch_bounds__(THREADS_G) void gather_row_kernel(
    const float* __restrict__ feat, float* __restrict__ out) {

    __shared__ int   sw[NX_];              // 1.7 KB
    __shared__ float tile[CCH * PITCH];    // 27.9 KB

    int t = threadIdx.x;
    int p = blockIdx.x;                    // 0 .. B*NY-1  (1984)
    int cell0 = p * NX_;                   // contiguous winner segment

    // Phase 0: copy winners to SMEM, then zero them for the next replay.
    if (t < NX_ / 4) {
        int4 w4 = g_winner4[cell0 / 4 + t];
        *reinterpret_cast<int4*>(sw + 4 * t) = w4;
        g_winner4[cell0 / 4 + t] = make_int4(0, 0, 0, 0);
    }
    __syncthreads();

    int b = p / NY_;
    int y = p - b * NY_;
    size_t rowbase = ((size_t)(b * C_) * NY_ + y) * NX_;

    bool active = (t < NX_);
    const float4* src = nullptr;
    if (active) {
        int w = sw[t];
        if (w > 0) src = reinterpret_cast<const float4*>(feat + (size_t)(w - 1) * C_);
    }
    const float4 z4 = make_float4(0.f, 0.f, 0.f, 0.f);

    // Prefetch chunk 0 (overlaps the winner-reset stores above).
    float4 v0 = z4, v1 = z4, v2 = z4, v3 = z4;
    if (src) { v0 = src[0]; v1 = src[1]; v2 = src[2]; v3 = src[3]; }

    #pragma unroll
    for (int ci = 0; ci < C_ / CCH; ci++) {
        // Phase 2: register -> transposed SMEM (16 stride-1 STS, no waits)
        if (active) {
            tile[ 0 * PITCH + t] = v0.x;  tile[ 1 * PITCH + t] = v0.y;
            tile[ 2 * PITCH + t] = v0.z;  tile[ 3 * PITCH + t] = v0.w;
            tile[ 4 * PITCH + t] = v1.x;  tile[ 5 * PITCH + t] = v1.y;
            tile[ 6 * PITCH + t] = v1.z;  tile[ 7 * PITCH + t] = v1.w;
            tile[ 8 * PITCH + t] = v2.x;  tile[ 9 * PITCH + t] = v2.y;
            tile[10 * PITCH + t] = v2.z;  tile[11 * PITCH + t] = v2.w;
            tile[12 * PITCH + t] = v3.x;  tile[13 * PITCH + t] = v3.y;
            tile[14 * PITCH + t] = v3.z;  tile[15 * PITCH + t] = v3.w;
        }
        __syncthreads();

        // Prefetch chunk ci+1: LDGs fly concurrently with phase-3 below.
        float4 n0 = z4, n1 = z4, n2 = z4, n3 = z4;
        if (ci + 1 < C_ / CCH && src) {
            const float4* s = src + (ci + 1) * 4;
            n0 = s[0]; n1 = s[1]; n2 = s[2]; n3 = s[3];
        }

        // Phase 3: 16 channels * 108 float4 = 1728 vector stores
        int cc = ci * CCH;
        for (int q = t; q < CCH * (NX_ / 4); q += THREADS_G) {
            int k = q / (NX_ / 4);
            int g = q - k * (NX_ / 4);
            float4 v = *reinterpret_cast<const float4*>(&tile[k * PITCH + g * 4]);
            *reinterpret_cast<float4*>(
                out + rowbase + (size_t)(cc + k) * (NY_ * NX_) + g * 4) = v;
        }
        __syncthreads();

        v0 = n0; v1 = n1; v2 = n2; v3 = n3;
    }
}

// ---------------------------------------------------------------------------
extern "C" void kernel_launch(void* const* d_in, const int* in_sizes, int n_in,
                              void* d_out, int out_size) {
    const float* feat  = (const float*)d_in[0];   // [N, 64] float32
    const int*   coors = (const int*)d_in[1];     // [N, 4] int32
    (void)n_in; (void)out_size;

    int n = in_sizes[1] / 4;

    {   // 1) atomicMax (point index + 1); winner array is all-zero on entry
        int threads = 256;
        int blocks  = (n + threads - 1) / threads;
        scatter_winner_kernel<<<blocks, threads>>>(coors, n);
    }
    {   // 2) pipelined row gather + transpose (+ winner reset for next replay)
        int blocks = B_ * NY_;   // 1984
        gather_row_kernel<<<blocks, THREADS_G>>>(feat, (float*)d_out);
    }
}